// round 17
// baseline (speedup 1.0000x reference)
#include <cuda_runtime.h>
#include <cuda_fp16.h>
#include <cstdint>

typedef unsigned int u32;

#define B_TOT   4096
#define K_STEPS 512
#define M_ROWS  16
#define THREADS 256

#define H16_P 136
#define X16_P 40
#define HW_P  136
#define WIH_P 40
#define WZN_P 136

// dynamic smem byte offsets (per CTA ~114 KB -> 2 CTAs/SM)
#define HB0_OFF  0        // 16*136*2 = 4352
#define HB1_OFF  4352
#define X16_OFF  8704     // 16*40*2 = 1280
#define WIH_OFF  9984     // 3*128*40*2 = 30720
#define WZN_OFF  40704    // 2*128*136*2 = 69632 (W_hh z,n gates)
#define HW_OFF   110336   // 8*136*2 = 2176
#define F32_OFF  112512   // 440 floats = 1760
#define SMEM_TOTAL 114304

#define BAR_SYNC(id, cnt)   asm volatile("bar.sync %0, %1;"   :: "r"(id), "r"(cnt) : "memory")
#define BAR_ARRIVE(id, cnt) asm volatile("bar.arrive %0, %1;" :: "r"(id), "r"(cnt) : "memory")

__device__ __forceinline__ u32 packh2(float a, float b) {
    __half2 h = __floats2half2_rn(a, b);
    return *(u32*)&h;
}
__device__ __forceinline__ float tanh_fast(float x) {
    float r; asm("tanh.approx.f32 %0,%1;" : "=f"(r) : "f"(x)); return r;
}
__device__ __forceinline__ float sig_fast(float x) {
    return fmaf(tanh_fast(0.5f * x), 0.5f, 0.5f);
}
__device__ __forceinline__ void rhs5(const float* y, const float* th, float* d) {
    float f1 = th[0] * y[0] - th[4] * y[1];
    float f2 = th[1] * y[1] - th[5] * y[2];
    float f3 = th[2] * y[2] - th[6] * y[3];
    float f4 = th[3] * y[3] - th[7] * y[4];
    d[0] = -f1; d[1] = f1 - f2; d[2] = f2 - f3; d[3] = f3 - f4; d[4] = f4;
}
__device__ __forceinline__ void mma4(float* c, const u32* a, u32 b0, u32 b1) {
    asm volatile(
        "mma.sync.aligned.m16n8k16.row.col.f32.f16.f16.f32 "
        "{%0,%1,%2,%3},{%4,%5,%6,%7},{%8,%9},{%0,%1,%2,%3};"
        : "+f"(c[0]), "+f"(c[1]), "+f"(c[2]), "+f"(c[3])
        : "r"(a[0]), "r"(a[1]), "r"(a[2]), "r"(a[3]), "r"(b0), "r"(b1));
}
__device__ __forceinline__ void ldsm4(u32* a, u32 sa) {
    asm volatile("ldmatrix.sync.aligned.m8n8.x4.shared.b16 {%0,%1,%2,%3},[%4];"
        : "=r"(a[0]), "=r"(a[1]), "=r"(a[2]), "=r"(a[3]) : "r"(sa));
}

__global__ void __launch_bounds__(THREADS, 2)
rnn_main(const float* __restrict__ y0,
         const float* __restrict__ u_seq,
         const float* __restrict__ dt_seq,
         const float* __restrict__ lift_W,
         const float* __restrict__ lift_b,
         const float* __restrict__ W_ih,
         const float* __restrict__ W_hh,
         const float* __restrict__ b_ih,
         const float* __restrict__ b_hh,
         const float* __restrict__ head_W,
         const float* __restrict__ head_b,
         const float* __restrict__ ujump,
         float* __restrict__ y_out,
         float* __restrict__ theta_out) {
    extern __shared__ char smc[];
    __half* hbuf0 = (__half*)(smc + HB0_OFF);
    __half* hbuf1 = (__half*)(smc + HB1_OFF);
    __half* x16   = (__half*)(smc + X16_OFF);
    __half* wih16 = (__half*)(smc + WIH_OFF);
    __half* wzn16 = (__half*)(smc + WZN_OFF);
    __half* hW16  = (__half*)(smc + HW_OFF);
    float*  fm    = (float*)(smc + F32_OFF);
    float* lW_s = fm;          // 256
    float* lb_s = fm + 256;    // 32
    float* hb_s = fm + 288;    // 8
    float* uj_s = fm + 296;    // 16
    float* th_s = fm + 312;    // 128

    const int t = threadIdx.x, w = t >> 5, lane = t & 31;
    const int qr = lane >> 2, qc = lane & 3;
    const int R0 = blockIdx.x * M_ROWS;
    const int wj = w * 16;
    const int j_lo = wj + qr, j_hi = j_lo + 8;
    const int lm = lane >> 3;

    // ---------------- prologue: smem staging ----------------
    for (int i = t; i < M_ROWS * H16_P / 2; i += THREADS) {
        ((u32*)hbuf0)[i] = 0;
        ((u32*)hbuf1)[i] = 0;
    }
    for (int i = t; i < 3 * 128 * 32; i += THREADS) {
        int g = i >> 12, rem = i & 4095, jj = rem >> 5, l = rem & 31;
        wih16[g * 128 * WIH_P + jj * WIH_P + l] = __float2half_rn(W_ih[i]);
    }
    for (int i = t; i < 2 * 128 * 128; i += THREADS) {
        int g = i >> 14, rem = i & 16383, jj = rem >> 7, kk = rem & 127;
        wzn16[g * 128 * WZN_P + jj * WZN_P + kk] =
            __float2half_rn(W_hh[((g + 1) * 128 + jj) * 128 + kk]);
    }
    for (int i = t; i < 1024; i += THREADS) {
        int c = i >> 7, kk = i & 127;
        hW16[c * HW_P + kk] = __float2half_rn(head_W[i]);
    }
    for (int i = t; i < 256; i += THREADS) lW_s[i] = lift_W[i];
    if (t < 32) lb_s[t] = lift_b[t];
    if (t < 8)  hb_s[t] = head_b[t];
    if (t < 15) uj_s[t] = ujump[t];

    // A fragments: r-gate W_hh in registers (z,n via ldsm)
    u32 aghR[8][4];
    #pragma unroll
    for (int s = 0; s < 8; ++s) {
        const float* p = W_hh + j_lo * 128 + 16 * s + qc * 2;
        aghR[s][0] = packh2(p[0], p[1]);
        aghR[s][1] = packh2(p[1024], p[1025]);
        aghR[s][2] = packh2(p[8], p[9]);
        aghR[s][3] = packh2(p[1032], p[1033]);
    }
    const float bR0  = b_ih[j_lo] + b_hh[j_lo];
    const float bR1  = b_ih[j_hi] + b_hh[j_hi];
    const float bZ0  = b_ih[128 + j_lo] + b_hh[128 + j_lo];
    const float bZ1  = b_ih[128 + j_hi] + b_hh[128 + j_hi];
    const float bNI0 = b_ih[256 + j_lo], bNI1 = b_ih[256 + j_hi];
    const float bNH0 = b_hh[256 + j_lo], bNH1 = b_hh[256 + j_hi];

    u32 smb;
    asm("{ .reg .u64 tt; cvta.to.shared.u64 tt, %1; cvt.u32.u64 %0, tt; }"
        : "=r"(smb) : "l"((const void*)smc));
    const u32 wih_lane = smb + WIH_OFF +
        (u32)((wj + (lm & 1) * 8 + (lane & 7)) * WIH_P + (lm >> 1) * 8) * 2u;
    const u32 wzn_lane = smb + WZN_OFF +
        (u32)((wj + (lm & 1) * 8 + (lane & 7)) * WZN_P + (lm >> 1) * 8) * 2u;
    // head ldsm base (w1): rows 0-15 of h buffer
    const u32 head_row_off =
        (u32)(((lm & 1) * 8 + (lane & 7)) * H16_P + (lm >> 1) * 8) * 2u;

    // tail state (w0, lane<16): row = lane
    const int rkrow = lane;
    float y[5] = {0, 0, 0, 0, 0};
    float uc0 = 0, uc1 = 0, uc2 = 0, dtc = 0;
    if (w == 0 && lane < 16) {
        #pragma unroll
        for (int i = 0; i < 5; ++i) y[i] = y0[(R0 + rkrow) * 5 + i] + 0.01f;
        const float* up = u_seq + ((size_t)(R0 + rkrow) * K_STEPS) * 3;
        uc0 = up[0]; uc1 = up[1]; uc2 = up[2];
        dtc = dt_seq[(size_t)(R0 + rkrow) * K_STEPS];
    }

    float cR[2][4], cZ[2][4], cNI[2][4], cNH[2][4];
    float hp_[2][4] = {{0,0,0,0},{0,0,0,0}};

    auto init_accs = [&]() {
        #pragma unroll
        for (int nt = 0; nt < 2; ++nt) {
            cR[nt][0] = bR0;  cR[nt][1] = bR0;  cR[nt][2] = bR1;  cR[nt][3] = bR1;
            cZ[nt][0] = bZ0;  cZ[nt][1] = bZ0;  cZ[nt][2] = bZ1;  cZ[nt][3] = bZ1;
            cNI[nt][0] = bNI0; cNI[nt][1] = bNI0; cNI[nt][2] = bNI1; cNI[nt][3] = bNI1;
            cNH[nt][0] = bNH0; cNH[nt][1] = bNH0; cNH[nt][2] = bNH1; cNH[nt][3] = bNH1;
        }
    };
    auto do_gh = [&](const __half* hb) {
        #pragma unroll
        for (int s = 0; s < 8; ++s) {
            u32 aZ[4], aN[4];
            ldsm4(aZ, wzn_lane + (u32)s * 32u);
            ldsm4(aN, wzn_lane + 34816u + (u32)s * 32u);
            #pragma unroll
            for (int nt = 0; nt < 2; ++nt) {
                const __half* hp = hb + (qr + 8 * nt) * H16_P + 16 * s + qc * 2;
                u32 b0 = *(const u32*)hp;
                u32 b1 = *(const u32*)(hp + 8);
                mma4(cR[nt],  aghR[s], b0, b1);
                mma4(cZ[nt],  aZ, b0, b1);
                mma4(cNH[nt], aN, b0, b1);
            }
        }
    };
    auto do_gi = [&]() {
        #pragma unroll
        for (int s = 0; s < 2; ++s) {
            u32 aR_[4], aZ_[4], aN_[4];
            ldsm4(aR_, wih_lane + (u32)s * 32u);
            ldsm4(aZ_, wih_lane + 10240u + (u32)s * 32u);
            ldsm4(aN_, wih_lane + 20480u + (u32)s * 32u);
            #pragma unroll
            for (int nt = 0; nt < 2; ++nt) {
                const __half* xp = x16 + (qr + 8 * nt) * X16_P + 16 * s + qc * 2;
                u32 b0 = *(const u32*)xp;
                u32 b1 = *(const u32*)(xp + 8);
                mma4(cR[nt],  aR_, b0, b1);
                mma4(cZ[nt],  aZ_, b0, b1);
                mma4(cNI[nt], aN_, b0, b1);
            }
        }
    };
    auto epilogue = [&](__half* hb) {
        #pragma unroll
        for (int nt = 0; nt < 2; ++nt) {
            int r0 = qc * 2 + 8 * nt;
            float hn[4];
            #pragma unroll
            for (int c = 0; c < 4; ++c) {
                float gr = sig_fast(cR[nt][c]);
                float gz = sig_fast(cZ[nt][c]);
                float gn = tanh_fast(fmaf(gr, cNH[nt][c], cNI[nt][c]));
                hn[c] = (1.f - gz) * gn + gz * hp_[nt][c];
                hp_[nt][c] = hn[c];
            }
            hb[r0 * H16_P + j_lo]       = __float2half_rn(hn[0]);
            hb[(r0 + 1) * H16_P + j_lo] = __float2half_rn(hn[1]);
            hb[r0 * H16_P + j_hi]       = __float2half_rn(hn[2]);
            hb[(r0 + 1) * H16_P + j_hi] = __float2half_rn(hn[3]);
        }
    };
    // lift one row in-lane (y in regs)
    auto lift_row = [&](int row, float u0, float u1, float u2) {
        float f[8];
        f[0] = u0; f[1] = u1; f[2] = u2;
        #pragma unroll
        for (int i = 0; i < 5; ++i) f[3 + i] = y[i];
        #pragma unroll
        for (int lp = 0; lp < 16; ++lp) {
            int l0 = lp * 2;
            const float4* wp = (const float4*)(lW_s + l0 * 8);
            float4 wa = wp[0], wb = wp[1], wc = wp[2], wd = wp[3];
            float a0 = lb_s[l0], a1 = lb_s[l0 + 1];
            a0 = fmaf(wa.x, f[0], a0); a0 = fmaf(wa.y, f[1], a0);
            a0 = fmaf(wa.z, f[2], a0); a0 = fmaf(wa.w, f[3], a0);
            a0 = fmaf(wb.x, f[4], a0); a0 = fmaf(wb.y, f[5], a0);
            a0 = fmaf(wb.z, f[6], a0); a0 = fmaf(wb.w, f[7], a0);
            a1 = fmaf(wc.x, f[0], a1); a1 = fmaf(wc.y, f[1], a1);
            a1 = fmaf(wc.z, f[2], a1); a1 = fmaf(wc.w, f[3], a1);
            a1 = fmaf(wd.x, f[4], a1); a1 = fmaf(wd.y, f[5], a1);
            a1 = fmaf(wd.z, f[6], a1); a1 = fmaf(wd.w, f[7], a1);
            *(u32*)&x16[row * X16_P + l0] =
                packh2(a0 * sig_fast(a0), a1 * sig_fast(a1));
        }
    };

    __syncthreads();
    if (w == 0 && lane < 16) lift_row(rkrow, uc0, uc1, uc2);
    __syncthreads();
    init_accs();
    do_gi();

    // ---------------- main loop ----------------
    // barA(__syncthreads): h(k) visible
    // bar id4 (cnt 64, w0+w1): theta ready (w1 arrive, w0 sync)
    // barB(__syncthreads): x(k+1) visible + gh reads done
    for (int k = 0; k < K_STEPS; ++k) {
        __half* hb_cur = (k & 1) ? hbuf1 : hbuf0;

        // early u/dt prefetch (LDGs in flight during epilogue)
        float un0 = 0, un1 = 0, un2 = 0, dtn = 0;
        if (w == 0 && lane < 16 && k + 1 < K_STEPS) {
            const float* up = u_seq + ((size_t)(R0 + rkrow) * K_STEPS + (k + 1)) * 3;
            un0 = up[0]; un1 = up[1]; un2 = up[2];
            dtn = dt_seq[(size_t)(R0 + rkrow) * K_STEPS + (k + 1)];
        }

        epilogue(hb_cur);                 // h(k) -> buf[k&1]
        __syncthreads();                  // A: h(k) visible

        if (w == 1) {
            // head(k): 16-row tile
            float cH[4];
            cH[0] = hb_s[qc * 2]; cH[1] = hb_s[qc * 2 + 1];
            cH[2] = cH[0];        cH[3] = cH[1];
            u32 a_lane = smb + ((k & 1) ? HB1_OFF : HB0_OFF) + head_row_off;
            #pragma unroll
            for (int s = 0; s < 8; ++s) {
                u32 a[4];
                ldsm4(a, a_lane + (u32)s * 32u);
                u32 b0 = *(const u32*)&hW16[qr * HW_P + 16 * s + qc * 2];
                u32 b1 = *(const u32*)&hW16[qr * HW_P + 16 * s + 8 + qc * 2];
                mma4(cH, a, b0, b1);
            }
            int row0 = qr, row1 = qr + 8;
            float t00 = fmaf(2.99f, sig_fast(cH[0]), 0.01f);
            float t01 = fmaf(2.99f, sig_fast(cH[1]), 0.01f);
            float t10 = fmaf(2.99f, sig_fast(cH[2]), 0.01f);
            float t11 = fmaf(2.99f, sig_fast(cH[3]), 0.01f);
            th_s[row0 * 8 + qc * 2]     = t00;
            th_s[row0 * 8 + qc * 2 + 1] = t01;
            th_s[row1 * 8 + qc * 2]     = t10;
            th_s[row1 * 8 + qc * 2 + 1] = t11;
            size_t ob0 = (((size_t)(R0 + row0)) * K_STEPS + k) * 8 + qc * 2;
            size_t ob1 = (((size_t)(R0 + row1)) * K_STEPS + k) * 8 + qc * 2;
            theta_out[ob0] = t00; theta_out[ob0 + 1] = t01;
            theta_out[ob1] = t10; theta_out[ob1 + 1] = t11;
            BAR_ARRIVE(4, 64);             // theta ready
            if (k + 1 < K_STEPS) { init_accs(); do_gh(hb_cur); }
        } else if (w == 0) {
            // gh first (overlaps w1's head), then RK4+lift
            if (k + 1 < K_STEPS) { init_accs(); do_gh(hb_cur); }
            BAR_SYNC(4, 64);               // wait theta

            if (lane < 16) {
                #pragma unroll
                for (int p = 0; p < 5; ++p)
                    y[p] += uc0 * uj_s[p] + uc1 * uj_s[5 + p] + uc2 * uj_s[10 + p];
                float th[8];
                #pragma unroll
                for (int i = 0; i < 8; ++i) th[i] = th_s[rkrow * 8 + i];
                float hs = dtc * 0.1f, hh = 0.5f * hs, h6 = hs * (1.f / 6.f);
                for (int s = 0; s < 10; ++s) {
                    float kk[5], yt[5], incr[5];
                    rhs5(y, th, kk);
                    #pragma unroll
                    for (int i = 0; i < 5; ++i) {
                        incr[i] = kk[i];
                        yt[i] = fmaf(hh, kk[i], y[i]);
                    }
                    rhs5(yt, th, kk);
                    #pragma unroll
                    for (int i = 0; i < 5; ++i) {
                        incr[i] = fmaf(2.f, kk[i], incr[i]);
                        yt[i] = fmaf(hh, kk[i], y[i]);
                    }
                    rhs5(yt, th, kk);
                    #pragma unroll
                    for (int i = 0; i < 5; ++i) {
                        incr[i] = fmaf(2.f, kk[i], incr[i]);
                        yt[i] = fmaf(hs, kk[i], y[i]);
                    }
                    rhs5(yt, th, kk);
                    #pragma unroll
                    for (int i = 0; i < 5; ++i) {
                        incr[i] += kk[i];
                        y[i] = fmaxf(fmaf(h6, incr[i], y[i]), 0.f);
                    }
                }
                // lift first (x on critical path), y_out STG after
                if (k + 1 < K_STEPS) {
                    lift_row(rkrow, un0, un1, un2);
                    uc0 = un0; uc1 = un1; uc2 = un2; dtc = dtn;
                }
                #pragma unroll
                for (int i = 0; i < 5; ++i)
                    y_out[(((size_t)(R0 + rkrow)) * K_STEPS + k) * 5 + i] = y[i];
            }
        } else {
            if (k + 1 < K_STEPS) { init_accs(); do_gh(hb_cur); }
        }
        __syncthreads();                  // B: x(k+1) visible, gh reads done

        if (k + 1 < K_STEPS) do_gi();
    }
}

extern "C" void kernel_launch(void* const* d_in, const int* in_sizes, int n_in,
                              void* d_out, int out_size) {
    const float* y0     = (const float*)d_in[0];
    const float* u_seq  = (const float*)d_in[1];
    const float* dt_seq = (const float*)d_in[2];
    const float* lift_W = (const float*)d_in[3];
    const float* lift_b = (const float*)d_in[4];
    const float* W_ih   = (const float*)d_in[5];
    const float* W_hh   = (const float*)d_in[6];
    const float* b_ih   = (const float*)d_in[7];
    const float* b_hh   = (const float*)d_in[8];
    const float* head_W = (const float*)d_in[9];
    const float* head_b = (const float*)d_in[10];
    const float* ujump  = (const float*)d_in[11];

    float* y_out     = (float*)d_out;
    float* theta_out = y_out + (size_t)B_TOT * K_STEPS * 5;

    cudaFuncSetAttribute(rnn_main, cudaFuncAttributeMaxDynamicSharedMemorySize,
                         SMEM_TOTAL);
    rnn_main<<<B_TOT / M_ROWS, THREADS, SMEM_TOTAL>>>(
        y0, u_seq, dt_seq, lift_W, lift_b, W_ih, W_hh, b_ih, b_hh,
        head_W, head_b, ujump, y_out, theta_out);
}